// round 3
// baseline (speedup 1.0000x reference)
#include <cuda_runtime.h>
#include <cuda_bf16.h>

#define N_NODES 100000
#define N_EDGES 1600000
#define DIM 128

// Intermediate h = x@W + b (100000 x 128 f32 = 51.2 MB). Static device scratch:
// the sanctioned allocation-free workaround.
__device__ float g_h[N_NODES * DIM];

// ---------------------------------------------------------------------------
// Kernel 0: zero the (poisoned) output buffer. 12.8M floats as float4.
// ---------------------------------------------------------------------------
__global__ void __launch_bounds__(256)
gcn_zero_kernel(float4* __restrict__ out4) {
    const int i = blockIdx.x * 256 + threadIdx.x;
    if (i < (N_NODES * DIM) / 4)
        out4[i] = make_float4(0.f, 0.f, 0.f, 0.f);
}

// ---------------------------------------------------------------------------
// Kernel 1: h = x @ W + b
// x tile staged in static smem (8 warps x 8 rows x 128 = 32 KB).
// W streamed from global: identical addresses across all warps/blocks -> L1
// resident (64 KB). Each warp: 8 rows; each lane: 4 output cols (float4).
// FMA-pipe-bound by design.
// ---------------------------------------------------------------------------
__global__ void __launch_bounds__(256)
gcn_gemm_kernel(const float* __restrict__ x, const float* __restrict__ W,
                const float* __restrict__ b) {
    __shared__ float xs[8 * 8 * DIM];  // 32 KB static smem (no opt-in needed)

    const int tid  = threadIdx.x;
    const int warp = tid >> 5;
    const int lane = tid & 31;
    const int c4   = lane * 4;

    float* xw = xs + warp * (8 * DIM);
    const int rowbase = blockIdx.x * 64 + warp * 8;

    // Stage this warp's 8 x-rows (coalesced float4 per lane per row).
#pragma unroll
    for (int rr = 0; rr < 8; rr++) {
        const int row = rowbase + rr;
        float4 xv = make_float4(0.f, 0.f, 0.f, 0.f);
        if (row < N_NODES) xv = *(const float4*)(x + (size_t)row * DIM + c4);
        *(float4*)(xw + rr * DIM + c4) = xv;
    }
    __syncwarp();

    float4 acc[8];
#pragma unroll
    for (int rr = 0; rr < 8; rr++) acc[rr] = make_float4(0.f, 0.f, 0.f, 0.f);

    const float4* Wg4 = (const float4*)W;  // W[k][c], row-major, 32 float4 per k

#pragma unroll 4
    for (int k4 = 0; k4 < DIM / 4; k4++) {
        // 8 broadcast LDS.128: 4 consecutive k-values per row.
        float4 xv[8];
#pragma unroll
        for (int rr = 0; rr < 8; rr++)
            xv[rr] = *(const float4*)(xw + rr * DIM + k4 * 4);

#pragma unroll
        for (int j = 0; j < 4; j++) {
            const float4 w = __ldg(&Wg4[(size_t)(k4 * 4 + j) * (DIM / 4) + lane]);
#pragma unroll
            for (int rr = 0; rr < 8; rr++) {
                const float xk = (j == 0) ? xv[rr].x
                               : (j == 1) ? xv[rr].y
                               : (j == 2) ? xv[rr].z
                                          : xv[rr].w;
                acc[rr].x += xk * w.x;
                acc[rr].y += xk * w.y;
                acc[rr].z += xk * w.z;
                acc[rr].w += xk * w.w;
            }
        }
    }

    const float4 bv = *(const float4*)(b + c4);
#pragma unroll
    for (int rr = 0; rr < 8; rr++) {
        const int row = rowbase + rr;
        if (row < N_NODES) {
            float4 o;
            o.x = acc[rr].x + bv.x;
            o.y = acc[rr].y + bv.y;
            o.z = acc[rr].z + bv.z;
            o.w = acc[rr].w + bv.w;
            *(float4*)(g_h + (size_t)row * DIM + c4) = o;
        }
    }
}

// ---------------------------------------------------------------------------
// Kernel 2: out[rows[e]] += vals[e] * h[cols[e]]   (one warp per edge)
// Coalesced float4 gather of the h row; 4 scalar atomicAdd per lane (ptxas
// emits no-return REDG). h + out both fit in L2 together -> LTS-bound.
// ---------------------------------------------------------------------------
__global__ void __launch_bounds__(256)
gcn_scatter_kernel(const float* __restrict__ vals, const int* __restrict__ rows,
                   const int* __restrict__ cols, float* __restrict__ out) {
    const int e = (blockIdx.x * 256 + threadIdx.x) >> 5;
    if (e >= N_EDGES) return;
    const int lane = threadIdx.x & 31;

    const float v = vals[e];
    const int r = rows[e];
    const int c = cols[e];

    const float4 hv = *(const float4*)(g_h + (size_t)c * DIM + lane * 4);
    float* dst = out + (size_t)r * DIM + lane * 4;
    atomicAdd(dst + 0, v * hv.x);
    atomicAdd(dst + 1, v * hv.y);
    atomicAdd(dst + 2, v * hv.z);
    atomicAdd(dst + 3, v * hv.w);
}

// ---------------------------------------------------------------------------
// Launcher: ONLY default-config kernel launches (graph-capture safe).
// ---------------------------------------------------------------------------
extern "C" void kernel_launch(void* const* d_in, const int* in_sizes, int n_in,
                              void* d_out, int out_size) {
    const float* x    = (const float*)d_in[0];
    const float* W    = (const float*)d_in[1];
    const float* b    = (const float*)d_in[2];
    const float* vals = (const float*)d_in[3];
    const int*   rows = (const int*)d_in[4];
    const int*   cols = (const int*)d_in[5];
    float* out = (float*)d_out;

    (void)in_sizes; (void)n_in; (void)out_size;

    // Zero output (poisoned to 0xAA by the harness).
    gcn_zero_kernel<<<(N_NODES * DIM / 4 + 255) / 256, 256>>>((float4*)out);

    // GEMM into g_h.
    gcn_gemm_kernel<<<(N_NODES + 63) / 64, 256>>>(x, W, b);

    // Edge scatter with atomics.
    gcn_scatter_kernel<<<(N_EDGES + 7) / 8, 256>>>(vals, rows, cols, out);
}

// round 4
// speedup vs baseline: 2.6369x; 2.6369x over previous
#include <cuda_runtime.h>
#include <cuda_bf16.h>

#define N_NODES 100000
#define N_EDGES 1600000
#define DIM 128
#define SCAN_CHUNK 1024
#define NCHUNKS ((N_NODES + SCAN_CHUNK - 1) / SCAN_CHUNK)  // 98

// Static device scratch (allocation-free per harness rules).
__device__ float g_h[N_NODES * DIM];     // h = x@W + b          (51.2 MB)
__device__ int   g_cnt[N_NODES];         // per-row edge counts
__device__ int   g_part[NCHUNKS];        // per-chunk partial sums
__device__ int   g_off[N_NODES + 1];     // CSR row offsets
__device__ int   g_cur[N_NODES];         // bucket cursors
__device__ int   g_ecol[N_EDGES];        // bucketed cols          (6.4 MB)
__device__ float g_eval[N_EDGES];        // bucketed vals          (6.4 MB)

// ---------------------------------------------------------------------------
// GEMM: h = x @ W + b. x tile in static smem (32 KB); W via L1 (64 KB,
// shared addresses across all warps). Warp = 8 rows, lane = 4 cols.
// ---------------------------------------------------------------------------
__global__ void __launch_bounds__(256)
k_gemm(const float* __restrict__ x, const float* __restrict__ W,
       const float* __restrict__ b) {
    __shared__ float xs[8 * 8 * DIM];

    const int tid  = threadIdx.x;
    const int warp = tid >> 5;
    const int lane = tid & 31;
    const int c4   = lane * 4;

    float* xw = xs + warp * (8 * DIM);
    const int rowbase = blockIdx.x * 64 + warp * 8;

#pragma unroll
    for (int rr = 0; rr < 8; rr++) {
        const int row = rowbase + rr;
        float4 xv = make_float4(0.f, 0.f, 0.f, 0.f);
        if (row < N_NODES) xv = *(const float4*)(x + (size_t)row * DIM + c4);
        *(float4*)(xw + rr * DIM + c4) = xv;
    }
    __syncwarp();

    float4 acc[8];
#pragma unroll
    for (int rr = 0; rr < 8; rr++) acc[rr] = make_float4(0.f, 0.f, 0.f, 0.f);

    const float4* Wg4 = (const float4*)W;

#pragma unroll 4
    for (int k4 = 0; k4 < DIM / 4; k4++) {
        float4 xv[8];
#pragma unroll
        for (int rr = 0; rr < 8; rr++)
            xv[rr] = *(const float4*)(xw + rr * DIM + k4 * 4);

#pragma unroll
        for (int j = 0; j < 4; j++) {
            const float4 w = __ldg(&Wg4[(size_t)(k4 * 4 + j) * (DIM / 4) + lane]);
#pragma unroll
            for (int rr = 0; rr < 8; rr++) {
                const float xk = (j == 0) ? xv[rr].x
                               : (j == 1) ? xv[rr].y
                               : (j == 2) ? xv[rr].z
                                          : xv[rr].w;
                acc[rr].x += xk * w.x;
                acc[rr].y += xk * w.y;
                acc[rr].z += xk * w.z;
                acc[rr].w += xk * w.w;
            }
        }
    }

    const float4 bv = *(const float4*)(b + c4);
#pragma unroll
    for (int rr = 0; rr < 8; rr++) {
        const int row = rowbase + rr;
        if (row < N_NODES) {
            float4 o;
            o.x = acc[rr].x + bv.x;
            o.y = acc[rr].y + bv.y;
            o.z = acc[rr].z + bv.z;
            o.w = acc[rr].w + bv.w;
            *(float4*)(g_h + (size_t)row * DIM + c4) = o;
        }
    }
}

// ---------------------------------------------------------------------------
// CSR build: zero counts -> histogram -> two-level exclusive scan -> bucket.
// ---------------------------------------------------------------------------
__global__ void __launch_bounds__(256) k_zero_cnt() {
    const int i = blockIdx.x * 256 + threadIdx.x;
    if (i < N_NODES) g_cnt[i] = 0;
}

__global__ void __launch_bounds__(256) k_hist(const int* __restrict__ rows) {
    const int e = blockIdx.x * 256 + threadIdx.x;
    if (e < N_EDGES) atomicAdd(&g_cnt[rows[e]], 1);
}

// Per-chunk sums (grid = NCHUNKS, block = 256).
__global__ void __launch_bounds__(256) k_part() {
    __shared__ int s[256];
    const int base = blockIdx.x * SCAN_CHUNK;
    int sum = 0;
    for (int j = threadIdx.x; j < SCAN_CHUNK; j += 256) {
        const int i = base + j;
        sum += (i < N_NODES) ? g_cnt[i] : 0;
    }
    s[threadIdx.x] = sum;
    __syncthreads();
#pragma unroll
    for (int st = 128; st > 0; st >>= 1) {
        if (threadIdx.x < st) s[threadIdx.x] += s[threadIdx.x + st];
        __syncthreads();
    }
    if (threadIdx.x == 0) g_part[blockIdx.x] = s[0];
}

// Exclusive scan of the NCHUNKS partials (1 block, 128 threads; NCHUNKS<=128).
__global__ void __launch_bounds__(128) k_scanpart() {
    __shared__ int s[128];
    const int v = (threadIdx.x < NCHUNKS) ? g_part[threadIdx.x] : 0;
    s[threadIdx.x] = v;
    __syncthreads();
#pragma unroll
    for (int st = 1; st < 128; st <<= 1) {
        const int t = (threadIdx.x >= st) ? s[threadIdx.x - st] : 0;
        __syncthreads();
        s[threadIdx.x] += t;
        __syncthreads();
    }
    if (threadIdx.x < NCHUNKS) g_part[threadIdx.x] = s[threadIdx.x] - v;
}

// Per-chunk exclusive scan + chunk base (grid = NCHUNKS, block = 1024).
__global__ void __launch_bounds__(1024) k_scanchunk() {
    __shared__ int s[SCAN_CHUNK];
    const int i = blockIdx.x * SCAN_CHUNK + threadIdx.x;
    const int v = (i < N_NODES) ? g_cnt[i] : 0;
    s[threadIdx.x] = v;
    __syncthreads();
#pragma unroll
    for (int st = 1; st < SCAN_CHUNK; st <<= 1) {
        const int t = (threadIdx.x >= st) ? s[threadIdx.x - st] : 0;
        __syncthreads();
        s[threadIdx.x] += t;
        __syncthreads();
    }
    if (i < N_NODES) {
        const int excl = s[threadIdx.x] - v + g_part[blockIdx.x];
        g_off[i] = excl;
        g_cur[i] = excl;
    }
    if (i == 0) g_off[N_NODES] = N_EDGES;
}

__global__ void __launch_bounds__(256)
k_bucket(const int* __restrict__ rows, const int* __restrict__ cols,
         const float* __restrict__ vals) {
    const int e = blockIdx.x * 256 + threadIdx.x;
    if (e >= N_EDGES) return;
    const int p = atomicAdd(&g_cur[rows[e]], 1);
    g_ecol[p] = cols[e];
    g_eval[p] = vals[e];
}

// ---------------------------------------------------------------------------
// Aggregate: one warp per node, register accumulation, single write per row.
// No atomics. Unroll edges x2 for MLP.
// ---------------------------------------------------------------------------
__global__ void __launch_bounds__(256)
k_agg(float* __restrict__ out) {
    const int node = (blockIdx.x * 256 + threadIdx.x) >> 5;
    if (node >= N_NODES) return;
    const int lane = threadIdx.x & 31;
    const int c4 = lane * 4;

    const int start = g_off[node];
    const int end   = g_off[node + 1];

    float4 acc = make_float4(0.f, 0.f, 0.f, 0.f);

    int e = start;
    for (; e + 2 <= end; e += 2) {
        const int   c0 = g_ecol[e];
        const int   c1 = g_ecol[e + 1];
        const float v0 = g_eval[e];
        const float v1 = g_eval[e + 1];
        const float4 h0 = *(const float4*)(g_h + (size_t)c0 * DIM + c4);
        const float4 h1 = *(const float4*)(g_h + (size_t)c1 * DIM + c4);
        acc.x += v0 * h0.x + v1 * h1.x;
        acc.y += v0 * h0.y + v1 * h1.y;
        acc.z += v0 * h0.z + v1 * h1.z;
        acc.w += v0 * h0.w + v1 * h1.w;
    }
    if (e < end) {
        const int   c0 = g_ecol[e];
        const float v0 = g_eval[e];
        const float4 h0 = *(const float4*)(g_h + (size_t)c0 * DIM + c4);
        acc.x += v0 * h0.x;
        acc.y += v0 * h0.y;
        acc.z += v0 * h0.z;
        acc.w += v0 * h0.w;
    }

    *(float4*)(out + (size_t)node * DIM + c4) = acc;
}

// ---------------------------------------------------------------------------
// Launcher: plain kernel launches only (graph-capture safe).
// ---------------------------------------------------------------------------
extern "C" void kernel_launch(void* const* d_in, const int* in_sizes, int n_in,
                              void* d_out, int out_size) {
    const float* x    = (const float*)d_in[0];
    const float* W    = (const float*)d_in[1];
    const float* b    = (const float*)d_in[2];
    const float* vals = (const float*)d_in[3];
    const int*   rows = (const int*)d_in[4];
    const int*   cols = (const int*)d_in[5];
    float* out = (float*)d_out;

    (void)in_sizes; (void)n_in; (void)out_size;

    // GEMM into g_h.
    k_gemm<<<(N_NODES + 63) / 64, 256>>>(x, W, b);

    // CSR build.
    k_zero_cnt<<<(N_NODES + 255) / 256, 256>>>();
    k_hist<<<(N_EDGES + 255) / 256, 256>>>(rows);
    k_part<<<NCHUNKS, 256>>>();
    k_scanpart<<<1, 128>>>();
    k_scanchunk<<<NCHUNKS, 1024>>>();
    k_bucket<<<(N_EDGES + 255) / 256, 256>>>(rows, cols, vals);

    // Atomic-free aggregation (also covers output zeroing).
    k_agg<<<(N_NODES * 32 + 255) / 256, 256>>>(out);
}

// round 5
// speedup vs baseline: 2.7437x; 1.0405x over previous
#include <cuda_runtime.h>
#include <cuda_bf16.h>

#define N_NODES 100000
#define N_EDGES 1600000
#define DIM 128
#define SCAN_CHUNK 1024
#define NCHUNKS ((N_NODES + SCAN_CHUNK - 1) / SCAN_CHUNK)  // 98

typedef unsigned long long u64;

// Static device scratch (allocation-free per harness rules).
__device__ float g_h[N_NODES * DIM];     // h = x@W + b          (51.2 MB)
__device__ int   g_cnt[N_NODES];         // per-row edge counts
__device__ int   g_part[NCHUNKS];        // per-chunk partial sums
__device__ int   g_off[N_NODES + 1];     // CSR row offsets
__device__ int   g_cur[N_NODES];         // bucket cursors
__device__ int2  g_epack[N_EDGES];       // bucketed (col, val-bits)  (12.8 MB)

// ---- packed fp32x2 helpers (Blackwell; ptxas never auto-fuses these) ------
__device__ __forceinline__ u64 fma2(u64 a, u64 b, u64 c) {
    u64 d;
    asm("fma.rn.f32x2 %0, %1, %2, %3;" : "=l"(d) : "l"(a), "l"(b), "l"(c));
    return d;
}
__device__ __forceinline__ u64 add2(u64 a, u64 b) {
    u64 d;
    asm("add.rn.f32x2 %0, %1, %2;" : "=l"(d) : "l"(a), "l"(b));
    return d;
}
__device__ __forceinline__ u64 dup2(float x) {
    u64 d;
    unsigned xi = __float_as_uint(x);
    asm("mov.b64 %0, {%1, %1};" : "=l"(d) : "r"(xi));
    return d;
}
__device__ __forceinline__ u64 pack2(float lo, float hi) {
    u64 d;
    asm("mov.b64 %0, {%1, %2};"
        : "=l"(d) : "r"(__float_as_uint(lo)), "r"(__float_as_uint(hi)));
    return d;
}

// ---------------------------------------------------------------------------
// GEMM: h = x @ W + b, packed-f32x2 mainloop.
// x tile in static smem (32 KB). W streamed as ulonglong2 (L1-resident 64 KB,
// identical addresses across warps). Warp = 8 rows, lane = 4 cols packed as
// two b64 accumulators. FMA-pipe instr count halved vs scalar FFMA.
// ---------------------------------------------------------------------------
__global__ void __launch_bounds__(256)
k_gemm(const float* __restrict__ x, const float* __restrict__ W,
       const float* __restrict__ b) {
    __shared__ float xs[8 * 8 * DIM];

    const int tid  = threadIdx.x;
    const int warp = tid >> 5;
    const int lane = tid & 31;
    const int c4   = lane * 4;

    float* xw = xs + warp * (8 * DIM);
    const int rowbase = blockIdx.x * 64 + warp * 8;

#pragma unroll
    for (int rr = 0; rr < 8; rr++) {
        const int row = rowbase + rr;
        float4 xv = make_float4(0.f, 0.f, 0.f, 0.f);
        if (row < N_NODES) xv = *(const float4*)(x + (size_t)row * DIM + c4);
        *(float4*)(xw + rr * DIM + c4) = xv;
    }
    __syncwarp();

    u64 acclo[8], acchi[8];
#pragma unroll
    for (int rr = 0; rr < 8; rr++) { acclo[rr] = 0ull; acchi[rr] = 0ull; }

    // W as 16B vectors: row k holds 32 ulonglong2; lane owns index k*32+lane.
    const ulonglong2* Wg2 = (const ulonglong2*)W;

#pragma unroll 2
    for (int k4 = 0; k4 < DIM / 4; k4++) {
        float4 xv[8];
#pragma unroll
        for (int rr = 0; rr < 8; rr++)
            xv[rr] = *(const float4*)(xw + rr * DIM + k4 * 4);

#pragma unroll
        for (int j = 0; j < 4; j++) {
            const ulonglong2 w2 = __ldg(&Wg2[(size_t)(k4 * 4 + j) * 32 + lane]);
#pragma unroll
            for (int rr = 0; rr < 8; rr++) {
                const float xk = (j == 0) ? xv[rr].x
                               : (j == 1) ? xv[rr].y
                               : (j == 2) ? xv[rr].z
                                          : xv[rr].w;
                const u64 xkk = dup2(xk);
                acclo[rr] = fma2(xkk, w2.x, acclo[rr]);
                acchi[rr] = fma2(xkk, w2.y, acchi[rr]);
            }
        }
    }

    const float4 bv = *(const float4*)(b + c4);
    const u64 b01 = pack2(bv.x, bv.y);
    const u64 b23 = pack2(bv.z, bv.w);
#pragma unroll
    for (int rr = 0; rr < 8; rr++) {
        const int row = rowbase + rr;
        if (row < N_NODES) {
            ulonglong2 o;
            o.x = add2(acclo[rr], b01);
            o.y = add2(acchi[rr], b23);
            *(ulonglong2*)(g_h + (size_t)row * DIM + c4) = o;
        }
    }
}

// ---------------------------------------------------------------------------
// CSR build: zero counts -> histogram -> two-level exclusive scan -> bucket.
// ---------------------------------------------------------------------------
__global__ void __launch_bounds__(256) k_zero_cnt() {
    const int i = blockIdx.x * 256 + threadIdx.x;
    if (i < N_NODES) g_cnt[i] = 0;
}

__global__ void __launch_bounds__(256) k_hist(const int* __restrict__ rows) {
    const int e = blockIdx.x * 256 + threadIdx.x;
    if (e < N_EDGES) atomicAdd(&g_cnt[rows[e]], 1);
}

__global__ void __launch_bounds__(256) k_part() {
    __shared__ int s[256];
    const int base = blockIdx.x * SCAN_CHUNK;
    int sum = 0;
    for (int j = threadIdx.x; j < SCAN_CHUNK; j += 256) {
        const int i = base + j;
        sum += (i < N_NODES) ? g_cnt[i] : 0;
    }
    s[threadIdx.x] = sum;
    __syncthreads();
#pragma unroll
    for (int st = 128; st > 0; st >>= 1) {
        if (threadIdx.x < st) s[threadIdx.x] += s[threadIdx.x + st];
        __syncthreads();
    }
    if (threadIdx.x == 0) g_part[blockIdx.x] = s[0];
}

__global__ void __launch_bounds__(128) k_scanpart() {
    __shared__ int s[128];
    const int v = (threadIdx.x < NCHUNKS) ? g_part[threadIdx.x] : 0;
    s[threadIdx.x] = v;
    __syncthreads();
#pragma unroll
    for (int st = 1; st < 128; st <<= 1) {
        const int t = (threadIdx.x >= st) ? s[threadIdx.x - st] : 0;
        __syncthreads();
        s[threadIdx.x] += t;
        __syncthreads();
    }
    if (threadIdx.x < NCHUNKS) g_part[threadIdx.x] = s[threadIdx.x] - v;
}

__global__ void __launch_bounds__(1024) k_scanchunk() {
    __shared__ int s[SCAN_CHUNK];
    const int i = blockIdx.x * SCAN_CHUNK + threadIdx.x;
    const int v = (i < N_NODES) ? g_cnt[i] : 0;
    s[threadIdx.x] = v;
    __syncthreads();
#pragma unroll
    for (int st = 1; st < SCAN_CHUNK; st <<= 1) {
        const int t = (threadIdx.x >= st) ? s[threadIdx.x - st] : 0;
        __syncthreads();
        s[threadIdx.x] += t;
        __syncthreads();
    }
    if (i < N_NODES) {
        const int excl = s[threadIdx.x] - v + g_part[blockIdx.x];
        g_off[i] = excl;
        g_cur[i] = excl;
    }
    if (i == 0) g_off[N_NODES] = N_EDGES;
}

__global__ void __launch_bounds__(256)
k_bucket(const int* __restrict__ rows, const int* __restrict__ cols,
         const float* __restrict__ vals) {
    const int e = blockIdx.x * 256 + threadIdx.x;
    if (e >= N_EDGES) return;
    const int p = atomicAdd(&g_cur[rows[e]], 1);
    g_epack[p] = make_int2(cols[e], __float_as_int(vals[e]));
}

// ---------------------------------------------------------------------------
// Aggregate: one warp per node, register accumulation, single write per row.
// No atomics. Edge loop unrolled x4 for MLP; (col,val) as one 8B load.
// ---------------------------------------------------------------------------
__global__ void __launch_bounds__(256)
k_agg(float* __restrict__ out) {
    const int node = (blockIdx.x * 256 + threadIdx.x) >> 5;
    if (node >= N_NODES) return;
    const int lane = threadIdx.x & 31;
    const int c4 = lane * 4;

    const int start = g_off[node];
    const int end   = g_off[node + 1];

    float4 acc = make_float4(0.f, 0.f, 0.f, 0.f);

    int e = start;
    for (; e + 4 <= end; e += 4) {
        const int2 p0 = g_epack[e + 0];
        const int2 p1 = g_epack[e + 1];
        const int2 p2 = g_epack[e + 2];
        const int2 p3 = g_epack[e + 3];
        const float4 h0 = *(const float4*)(g_h + (size_t)p0.x * DIM + c4);
        const float4 h1 = *(const float4*)(g_h + (size_t)p1.x * DIM + c4);
        const float4 h2 = *(const float4*)(g_h + (size_t)p2.x * DIM + c4);
        const float4 h3 = *(const float4*)(g_h + (size_t)p3.x * DIM + c4);
        const float v0 = __int_as_float(p0.y);
        const float v1 = __int_as_float(p1.y);
        const float v2 = __int_as_float(p2.y);
        const float v3 = __int_as_float(p3.y);
        acc.x += v0 * h0.x + v1 * h1.x + v2 * h2.x + v3 * h3.x;
        acc.y += v0 * h0.y + v1 * h1.y + v2 * h2.y + v3 * h3.y;
        acc.z += v0 * h0.z + v1 * h1.z + v2 * h2.z + v3 * h3.z;
        acc.w += v0 * h0.w + v1 * h1.w + v2 * h2.w + v3 * h3.w;
    }
    for (; e < end; e++) {
        const int2 p0 = g_epack[e];
        const float v0 = __int_as_float(p0.y);
        const float4 h0 = *(const float4*)(g_h + (size_t)p0.x * DIM + c4);
        acc.x += v0 * h0.x;
        acc.y += v0 * h0.y;
        acc.z += v0 * h0.z;
        acc.w += v0 * h0.w;
    }

    *(float4*)(out + (size_t)node * DIM + c4) = acc;
}

// ---------------------------------------------------------------------------
// Launcher: plain kernel launches only (graph-capture safe).
// ---------------------------------------------------------------------------
extern "C" void kernel_launch(void* const* d_in, const int* in_sizes, int n_in,
                              void* d_out, int out_size) {
    const float* x    = (const float*)d_in[0];
    const float* W    = (const float*)d_in[1];
    const float* b    = (const float*)d_in[2];
    const float* vals = (const float*)d_in[3];
    const int*   rows = (const int*)d_in[4];
    const int*   cols = (const int*)d_in[5];
    float* out = (float*)d_out;

    (void)in_sizes; (void)n_in; (void)out_size;

    // GEMM into g_h (packed f32x2 path).
    k_gemm<<<(N_NODES + 63) / 64, 256>>>(x, W, b);

    // CSR build.
    k_zero_cnt<<<(N_NODES + 255) / 256, 256>>>();
    k_hist<<<(N_EDGES + 255) / 256, 256>>>(rows);
    k_part<<<NCHUNKS, 256>>>();
    k_scanpart<<<1, 128>>>();
    k_scanchunk<<<NCHUNKS, 1024>>>();
    k_bucket<<<(N_EDGES + 255) / 256, 256>>>(rows, cols, vals);

    // Atomic-free aggregation (also covers output zeroing).
    k_agg<<<(N_NODES * 32 + 255) / 256, 256>>>(out);
}

// round 6
// speedup vs baseline: 3.1473x; 1.1471x over previous
#include <cuda_runtime.h>
#include <cuda_fp16.h>

#define N_NODES 100000
#define N_EDGES 1600000
#define DIM 128
#define SCAN_CHUNK 1024
#define NCHUNKS ((N_NODES + SCAN_CHUNK - 1) / SCAN_CHUNK)  // 98
#define SCAN_FLAG (1 << 30)

typedef unsigned long long u64;

// Static device scratch (allocation-free per harness rules).
__device__ __half g_h[N_NODES * DIM];    // h = x@W + b, fp16    (25.6 MB)
__device__ int    g_cnt[N_NODES];        // per-row edge counts
__device__ int    g_aggf[NCHUNKS];       // lookback: aggregate | SCAN_FLAG
__device__ int    g_off[N_NODES + 1];    // CSR row offsets
__device__ int    g_cur[N_NODES];        // bucket cursors
__device__ int2   g_epack[N_EDGES];      // bucketed (col, val-bits) (12.8 MB)

// ---- packed fp32x2 helpers ------------------------------------------------
__device__ __forceinline__ u64 fma2(u64 a, u64 b, u64 c) {
    u64 d;
    asm("fma.rn.f32x2 %0, %1, %2, %3;" : "=l"(d) : "l"(a), "l"(b), "l"(c));
    return d;
}
__device__ __forceinline__ u64 add2(u64 a, u64 b) {
    u64 d;
    asm("add.rn.f32x2 %0, %1, %2;" : "=l"(d) : "l"(a), "l"(b));
    return d;
}
__device__ __forceinline__ u64 dup2(float x) {
    u64 d;
    unsigned xi = __float_as_uint(x);
    asm("mov.b64 %0, {%1, %1};" : "=l"(d) : "r"(xi));
    return d;
}
__device__ __forceinline__ u64 pack2(float lo, float hi) {
    u64 d;
    asm("mov.b64 %0, {%1, %2};"
        : "=l"(d) : "r"(__float_as_uint(lo)), "r"(__float_as_uint(hi)));
    return d;
}
__device__ __forceinline__ float2 unpk2(u64 d) {
    float2 f;
    asm("mov.b64 {%0, %1}, %2;" : "=f"(f.x), "=f"(f.y) : "l"(d));
    return f;
}

// ---------------------------------------------------------------------------
// GEMM: h = x @ W + b (fp32 math, fp16 store).
// x tile in static smem (32 KB); W via L1 (64 KB, shared addresses).
// Warp = 8 rows, lane = 4 cols as two packed b64 accumulators.
// ---------------------------------------------------------------------------
__global__ void __launch_bounds__(256)
k_gemm(const float* __restrict__ x, const float* __restrict__ W,
       const float* __restrict__ b) {
    __shared__ float xs[8 * 8 * DIM];

    const int tid  = threadIdx.x;
    const int warp = tid >> 5;
    const int lane = tid & 31;
    const int c4   = lane * 4;

    float* xw = xs + warp * (8 * DIM);
    const int rowbase = blockIdx.x * 64 + warp * 8;

#pragma unroll
    for (int rr = 0; rr < 8; rr++) {
        const int row = rowbase + rr;
        float4 xv = make_float4(0.f, 0.f, 0.f, 0.f);
        if (row < N_NODES) xv = *(const float4*)(x + (size_t)row * DIM + c4);
        *(float4*)(xw + rr * DIM + c4) = xv;
    }
    __syncwarp();

    u64 acclo[8], acchi[8];
#pragma unroll
    for (int rr = 0; rr < 8; rr++) { acclo[rr] = 0ull; acchi[rr] = 0ull; }

    const ulonglong2* Wg2 = (const ulonglong2*)W;

#pragma unroll 2
    for (int k4 = 0; k4 < DIM / 4; k4++) {
        float4 xv[8];
#pragma unroll
        for (int rr = 0; rr < 8; rr++)
            xv[rr] = *(const float4*)(xw + rr * DIM + k4 * 4);

#pragma unroll
        for (int j = 0; j < 4; j++) {
            const ulonglong2 w2 = __ldg(&Wg2[(size_t)(k4 * 4 + j) * 32 + lane]);
#pragma unroll
            for (int rr = 0; rr < 8; rr++) {
                const float xk = (j == 0) ? xv[rr].x
                               : (j == 1) ? xv[rr].y
                               : (j == 2) ? xv[rr].z
                                          : xv[rr].w;
                const u64 xkk = dup2(xk);
                acclo[rr] = fma2(xkk, w2.x, acclo[rr]);
                acchi[rr] = fma2(xkk, w2.y, acchi[rr]);
            }
        }
    }

    const float4 bv = *(const float4*)(b + c4);
    const u64 b01 = pack2(bv.x, bv.y);
    const u64 b23 = pack2(bv.z, bv.w);
#pragma unroll
    for (int rr = 0; rr < 8; rr++) {
        const int row = rowbase + rr;
        if (row < N_NODES) {
            const float2 f01 = unpk2(add2(acclo[rr], b01));
            const float2 f23 = unpk2(add2(acchi[rr], b23));
            const __half2 h01 = __floats2half2_rn(f01.x, f01.y);
            const __half2 h23 = __floats2half2_rn(f23.x, f23.y);
            uint2 o;
            o.x = *(const unsigned*)&h01;
            o.y = *(const unsigned*)&h23;
            *(uint2*)(g_h + (size_t)row * DIM + c4) = o;
        }
    }
}

// ---------------------------------------------------------------------------
// CSR build: zero -> histogram -> single-pass lookback scan -> bucket.
// ---------------------------------------------------------------------------
__global__ void __launch_bounds__(256) k_zero() {
    const int i = blockIdx.x * 256 + threadIdx.x;
    if (i < N_NODES) g_cnt[i] = 0;
    if (i < NCHUNKS) g_aggf[i] = 0;
}

__global__ void __launch_bounds__(256) k_hist(const int* __restrict__ rows) {
    const int e = blockIdx.x * 256 + threadIdx.x;
    if (e < N_EDGES) atomicAdd(&g_cnt[rows[e]], 1);
}

// Decoupled-lookback exclusive scan over g_cnt. 98 blocks (< 148 SMs): every
// block resident in wave 1, so polling predecessors cannot deadlock.
__global__ void __launch_bounds__(1024) k_scan() {
    __shared__ int s[SCAN_CHUNK];
    __shared__ int base_sh;
    const int blk = blockIdx.x;
    const int i = blk * SCAN_CHUNK + threadIdx.x;
    const int v = (i < N_NODES) ? g_cnt[i] : 0;
    s[threadIdx.x] = v;
    __syncthreads();
#pragma unroll
    for (int st = 1; st < SCAN_CHUNK; st <<= 1) {
        const int t = (threadIdx.x >= st) ? s[threadIdx.x - st] : 0;
        __syncthreads();
        s[threadIdx.x] += t;       // inclusive scan
        __syncthreads();
    }
    // Publish this block's aggregate (flag bit marks availability).
    if (threadIdx.x == SCAN_CHUNK - 1) {
        __threadfence();
        atomicExch(&g_aggf[blk], s[SCAN_CHUNK - 1] | SCAN_FLAG);
    }
    // Warp 0 looks back over all predecessors.
    if (threadIdx.x < 32) {
        int sum = 0;
        for (int p = (int)threadIdx.x; p < blk; p += 32) {
            int a;
            do { a = atomicAdd(&g_aggf[p], 0); } while (!(a & SCAN_FLAG));
            sum += a & ~SCAN_FLAG;
        }
#pragma unroll
        for (int o = 16; o > 0; o >>= 1) sum += __shfl_xor_sync(~0u, sum, o);
        if (threadIdx.x == 0) base_sh = sum;
    }
    __syncthreads();
    if (i < N_NODES) {
        const int excl = base_sh + s[threadIdx.x] - v;
        g_off[i] = excl;
        g_cur[i] = excl;
    }
    if (i == 0) g_off[N_NODES] = N_EDGES;
}

__global__ void __launch_bounds__(256)
k_bucket(const int* __restrict__ rows, const int* __restrict__ cols,
         const float* __restrict__ vals) {
    const int e = blockIdx.x * 256 + threadIdx.x;
    if (e >= N_EDGES) return;
    const int p = atomicAdd(&g_cur[rows[e]], 1);
    g_epack[p] = make_int2(cols[e], __float_as_int(vals[e]));
}

// ---------------------------------------------------------------------------
// Aggregate: one warp per node, fp32 accumulation over fp16 h rows.
// Lane loads 4 cols as one 8B gather; x4 edge unroll for MLP. No atomics.
// ---------------------------------------------------------------------------
__global__ void __launch_bounds__(256)
k_agg(float* __restrict__ out) {
    const int node = (blockIdx.x * 256 + threadIdx.x) >> 5;
    if (node >= N_NODES) return;
    const int lane = threadIdx.x & 31;
    const int c4 = lane * 4;

    const int start = g_off[node];
    const int end   = g_off[node + 1];

    float4 acc = make_float4(0.f, 0.f, 0.f, 0.f);

    int e = start;
    for (; e + 4 <= end; e += 4) {
#pragma unroll
        for (int q = 0; q < 4; q++) {
            const int2 p = g_epack[e + q];
            const float v = __int_as_float(p.y);
            const uint2 u = *(const uint2*)(g_h + (size_t)p.x * DIM + c4);
            const float2 f01 = __half22float2(*(const __half2*)&u.x);
            const float2 f23 = __half22float2(*(const __half2*)&u.y);
            acc.x += v * f01.x;
            acc.y += v * f01.y;
            acc.z += v * f23.x;
            acc.w += v * f23.y;
        }
    }
    for (; e < end; e++) {
        const int2 p = g_epack[e];
        const float v = __int_as_float(p.y);
        const uint2 u = *(const uint2*)(g_h + (size_t)p.x * DIM + c4);
        const float2 f01 = __half22float2(*(const __half2*)&u.x);
        const float2 f23 = __half22float2(*(const __half2*)&u.y);
        acc.x += v * f01.x;
        acc.y += v * f01.y;
        acc.z += v * f23.x;
        acc.w += v * f23.y;
    }

    *(float4*)(out + (size_t)node * DIM + c4) = acc;
}

// ---------------------------------------------------------------------------
// Launcher: plain kernel launches only (graph-capture safe). 6 launches.
// ---------------------------------------------------------------------------
extern "C" void kernel_launch(void* const* d_in, const int* in_sizes, int n_in,
                              void* d_out, int out_size) {
    const float* x    = (const float*)d_in[0];
    const float* W    = (const float*)d_in[1];
    const float* b    = (const float*)d_in[2];
    const float* vals = (const float*)d_in[3];
    const int*   rows = (const int*)d_in[4];
    const int*   cols = (const int*)d_in[5];
    float* out = (float*)d_out;

    (void)in_sizes; (void)n_in; (void)out_size;

    k_gemm<<<(N_NODES + 63) / 64, 256>>>(x, W, b);
    k_zero<<<(N_NODES + 255) / 256, 256>>>();
    k_hist<<<(N_EDGES + 255) / 256, 256>>>(rows);
    k_scan<<<NCHUNKS, SCAN_CHUNK>>>();
    k_bucket<<<(N_EDGES + 255) / 256, 256>>>(rows, cols, vals);
    k_agg<<<(N_NODES * 32 + 255) / 256, 256>>>(out);
}

// round 8
// speedup vs baseline: 4.3873x; 1.3940x over previous
#include <cuda_runtime.h>
#include <cuda_fp16.h>

#define N_NODES 100000
#define N_EDGES 1600000
#define DIM 128
#define SCAN_CHUNK 1024
#define NCHUNKS ((N_NODES + SCAN_CHUNK - 1) / SCAN_CHUNK)  // 98
#define SCAN_FLAG (1 << 30)

// Static device scratch (allocation-free per harness rules).
__device__ __half g_h[N_NODES * DIM];    // h = x@W + b, fp16    (25.6 MB)
__device__ int    g_cnt[N_NODES];        // per-row edge counts
__device__ int    g_aggf[NCHUNKS];       // lookback: aggregate | SCAN_FLAG
__device__ int    g_off[N_NODES + 1];    // CSR row offsets
__device__ int    g_cur[N_NODES];        // bucket cursors
__device__ int2   g_epack[N_EDGES];      // bucketed (col, val-bits) (12.8 MB)

// ---------------------------------------------------------------------------
// GEMM: h = x @ W + b via HMMA (m16n8k16, fp16 in / fp32 accumulate).
// Block = 128 threads (4 warps), tile 64 rows x 64 cols, K=128.
// x and W converted fp32->fp16 inline into XOR-swizzled smem; A via
// ldmatrix.x4, B via ldmatrix.x4.trans (2 n-tiles per ldmatrix).
// ---------------------------------------------------------------------------
__global__ void __launch_bounds__(128)
k_gemm(const float* __restrict__ x, const float* __restrict__ W,
       const float* __restrict__ b) {
    __shared__ __align__(16) __half xs[64 * 128];   // 16 KB, swizzled
    __shared__ __align__(16) __half ws[128 * 64];   // 16 KB, swizzled

    const int tid  = threadIdx.x;
    const int lane = tid & 31;
    const int warp = tid >> 5;
    const int rb   = blockIdx.x >> 1;
    const int cb   = blockIdx.x & 1;
    const int row0 = rb * 64;
    const int col0 = cb * 64;

    const unsigned xs_base = (unsigned)__cvta_generic_to_shared(xs);
    const unsigned ws_base = (unsigned)__cvta_generic_to_shared(ws);

    // Stage x tile: 64 rows x 128 cols, fp32 -> fp16, swizzle ^((row&7)<<4).
#pragma unroll
    for (int it = 0; it < 16; it++) {
        const int idx = tid + it * 128;
        const int r = idx >> 5;       // 0..63
        const int q = idx & 31;       // float4 quad
        const int grow = row0 + r;
        float4 v = make_float4(0.f, 0.f, 0.f, 0.f);
        if (grow < N_NODES) v = *(const float4*)(x + (size_t)grow * DIM + q * 4);
        const __half2 h01 = __floats2half2_rn(v.x, v.y);
        const __half2 h23 = __floats2half2_rn(v.z, v.w);
        const int byte = (r * 256 + q * 8) ^ ((r & 7) << 4);
        *(uint2*)((char*)xs + byte) =
            make_uint2(*(const unsigned*)&h01, *(const unsigned*)&h23);
    }
    // Stage W tile: 128 k x 64 n, swizzle ^((k&7)<<4).
#pragma unroll
    for (int it = 0; it < 16; it++) {
        const int idx = tid + it * 128;
        const int k = idx >> 4;       // 0..127
        const int q = idx & 15;       // float4 quad within 64 cols
        const float4 v = *(const float4*)(W + (size_t)k * DIM + col0 + q * 4);
        const __half2 h01 = __floats2half2_rn(v.x, v.y);
        const __half2 h23 = __floats2half2_rn(v.z, v.w);
        const int byte = (k * 128 + q * 8) ^ ((k & 7) << 4);
        *(uint2*)((char*)ws + byte) =
            make_uint2(*(const unsigned*)&h01, *(const unsigned*)&h23);
    }
    __syncthreads();

    float acc[8][4];
#pragma unroll
    for (int i = 0; i < 8; i++)
#pragma unroll
        for (int j = 0; j < 4; j++) acc[i][j] = 0.f;

    // A ldmatrix lane mapping: lanes 0-7 rows 0-7 @k, 8-15 rows 8-15 @k,
    // 16-23 rows 0-7 @k+8, 24-31 rows 8-15 @k+8.
    const int ar    = warp * 16 + (lane & 15);
    const int akoff = (lane >> 4) << 3;
    // B ldmatrix.x4.trans: matrix m = lane>>3; m0:(k,n) m1:(k+8,n) m2:(k,n+8) m3:(k+8,n+8)
    const int bm    = lane >> 3;
    const int bkrow = ((bm & 1) << 3) + (lane & 7);
    const int bnoff = (bm >> 1) << 3;

#pragma unroll
    for (int ks = 0; ks < 8; ks++) {
        const int k0 = ks * 16;
        unsigned a0, a1, a2, a3;
        {
            const int kk = k0 + akoff;
            const unsigned addr =
                xs_base + ((ar * 256 + kk * 2) ^ ((ar & 7) << 4));
            asm volatile(
                "ldmatrix.sync.aligned.m8n8.x4.shared.b16 {%0,%1,%2,%3}, [%4];"
                : "=r"(a0), "=r"(a1), "=r"(a2), "=r"(a3) : "r"(addr));
        }
#pragma unroll
        for (int p = 0; p < 4; p++) {
            unsigned b0, b1, b2, b3;
            const int kk = k0 + bkrow;
            const int nn = p * 16 + bnoff;
            const unsigned addr =
                ws_base + ((kk * 128 + nn * 2) ^ ((kk & 7) << 4));
            asm volatile(
                "ldmatrix.sync.aligned.m8n8.x4.trans.shared.b16 {%0,%1,%2,%3}, [%4];"
                : "=r"(b0), "=r"(b1), "=r"(b2), "=r"(b3) : "r"(addr));
            asm volatile(
                "mma.sync.aligned.m16n8k16.row.col.f32.f16.f16.f32 "
                "{%0,%1,%2,%3}, {%4,%5,%6,%7}, {%8,%9}, {%0,%1,%2,%3};"
                : "+f"(acc[2 * p][0]), "+f"(acc[2 * p][1]),
                  "+f"(acc[2 * p][2]), "+f"(acc[2 * p][3])
                : "r"(a0), "r"(a1), "r"(a2), "r"(a3), "r"(b0), "r"(b1));
            asm volatile(
                "mma.sync.aligned.m16n8k16.row.col.f32.f16.f16.f32 "
                "{%0,%1,%2,%3}, {%4,%5,%6,%7}, {%8,%9}, {%0,%1,%2,%3};"
                : "+f"(acc[2 * p + 1][0]), "+f"(acc[2 * p + 1][1]),
                  "+f"(acc[2 * p + 1][2]), "+f"(acc[2 * p + 1][3])
                : "r"(a0), "r"(a1), "r"(a2), "r"(a3), "r"(b2), "r"(b3));
        }
    }

    // Epilogue: +bias, fp16 store. acc c0,c1 -> row lane/4, cols (lane%4)*2,+1;
    // c2,c3 -> row+8.
    const int r0 = row0 + warp * 16 + (lane >> 2);
    const int r1 = r0 + 8;
    const int cbase = col0 + ((lane & 3) << 1);
#pragma unroll
    for (int i = 0; i < 8; i++) {
        const int n = cbase + i * 8;
        const float2 bb = *(const float2*)(b + n);
        const __half2 lo = __floats2half2_rn(acc[i][0] + bb.x, acc[i][1] + bb.y);
        const __half2 hi = __floats2half2_rn(acc[i][2] + bb.x, acc[i][3] + bb.y);
        if (r0 < N_NODES) *(__half2*)(g_h + (size_t)r0 * DIM + n) = lo;
        if (r1 < N_NODES) *(__half2*)(g_h + (size_t)r1 * DIM + n) = hi;
    }
}

// ---------------------------------------------------------------------------
// CSR build: zero -> histogram -> single-pass lookback scan -> bucket.
// ---------------------------------------------------------------------------
__global__ void __launch_bounds__(256) k_zero() {
    const int i = blockIdx.x * 256 + threadIdx.x;
    if (i < N_NODES) g_cnt[i] = 0;
    if (i < NCHUNKS) g_aggf[i] = 0;
}

__global__ void __launch_bounds__(256) k_hist(const int* __restrict__ rows) {
    const int e = blockIdx.x * 256 + threadIdx.x;
    if (e < N_EDGES) atomicAdd(&g_cnt[rows[e]], 1);
}

// Decoupled-lookback exclusive scan; 98 blocks < 148 SMs -> all wave-1 resident.
__global__ void __launch_bounds__(1024) k_scan() {
    __shared__ int s[SCAN_CHUNK];
    __shared__ int base_sh;
    const int blk = blockIdx.x;
    const int i = blk * SCAN_CHUNK + threadIdx.x;
    const int v = (i < N_NODES) ? g_cnt[i] : 0;
    s[threadIdx.x] = v;
    __syncthreads();
#pragma unroll
    for (int st = 1; st < SCAN_CHUNK; st <<= 1) {
        const int t = (threadIdx.x >= st) ? s[threadIdx.x - st] : 0;
        __syncthreads();
        s[threadIdx.x] += t;
        __syncthreads();
    }
    if (threadIdx.x == SCAN_CHUNK - 1) {
        __threadfence();
        atomicExch(&g_aggf[blk], s[SCAN_CHUNK - 1] | SCAN_FLAG);
    }
    if (threadIdx.x < 32) {
        int sum = 0;
        for (int p = (int)threadIdx.x; p < blk; p += 32) {
            int a;
            do { a = atomicAdd(&g_aggf[p], 0); } while (!(a & SCAN_FLAG));
            sum += a & ~SCAN_FLAG;
        }
#pragma unroll
        for (int o = 16; o > 0; o >>= 1) sum += __shfl_xor_sync(~0u, sum, o);
        if (threadIdx.x == 0) base_sh = sum;
    }
    __syncthreads();
    if (i < N_NODES) {
        const int excl = base_sh + s[threadIdx.x] - v;
        g_off[i] = excl;
        g_cur[i] = excl;
    }
    if (i == 0) g_off[N_NODES] = N_EDGES;
}

__global__ void __launch_bounds__(256)
k_bucket(const int* __restrict__ rows, const int* __restrict__ cols,
         const float* __restrict__ vals) {
    const int e = blockIdx.x * 256 + threadIdx.x;
    if (e >= N_EDGES) return;
    const int p = atomicAdd(&g_cur[rows[e]], 1);
    g_epack[p] = make_int2(cols[e], __float_as_int(vals[e]));
}

// ---------------------------------------------------------------------------
// Aggregate: one warp per node, fp32 accumulation over fp16 h rows.
// ---------------------------------------------------------------------------
__global__ void __launch_bounds__(256)
k_agg(float* __restrict__ out) {
    const int node = (blockIdx.x * 256 + threadIdx.x) >> 5;
    if (node >= N_NODES) return;
    const int lane = threadIdx.x & 31;
    const int c4 = lane * 4;

    const int start = g_off[node];
    const int end   = g_off[node + 1];

    float4 acc = make_float4(0.f, 0.f, 0.f, 0.f);

    int e = start;
    for (; e + 4 <= end; e += 4) {
#pragma unroll
        for (int q = 0; q < 4; q++) {
            const int2 p = g_epack[e + q];
            const float v = __int_as_float(p.y);
            const uint2 u = *(const uint2*)(g_h + (size_t)p.x * DIM + c4);
            const float2 f01 = __half22float2(*(const __half2*)&u.x);
            const float2 f23 = __half22float2(*(const __half2*)&u.y);
            acc.x += v * f01.x;
            acc.y += v * f01.y;
            acc.z += v * f23.x;
            acc.w += v * f23.y;
        }
    }
    for (; e < end; e++) {
        const int2 p = g_epack[e];
        const float v = __int_as_float(p.y);
        const uint2 u = *(const uint2*)(g_h + (size_t)p.x * DIM + c4);
        const float2 f01 = __half22float2(*(const __half2*)&u.x);
        const float2 f23 = __half22float2(*(const __half2*)&u.y);
        acc.x += v * f01.x;
        acc.y += v * f01.y;
        acc.z += v * f23.x;
        acc.w += v * f23.y;
    }

    *(float4*)(out + (size_t)node * DIM + c4) = acc;
}

// ---------------------------------------------------------------------------
// Launcher: plain kernel launches only (graph-capture safe). 6 launches.
// ---------------------------------------------------------------------------
extern "C" void kernel_launch(void* const* d_in, const int* in_sizes, int n_in,
                              void* d_out, int out_size) {
    const float* x    = (const float*)d_in[0];
    const float* W    = (const float*)d_in[1];
    const float* b    = (const float*)d_in[2];
    const float* vals = (const float*)d_in[3];
    const int*   rows = (const int*)d_in[4];
    const int*   cols = (const int*)d_in[5];
    float* out = (float*)d_out;

    (void)in_sizes; (void)n_in; (void)out_size;

    // HMMA GEMM into g_h: 1563 row-blocks x 2 col-blocks.
    k_gemm<<<((N_NODES + 63) / 64) * 2, 128>>>(x, W, b);

    // CSR build.
    k_zero<<<(N_NODES + 255) / 256, 256>>>();
    k_hist<<<(N_EDGES + 255) / 256, 256>>>(rows);
    k_scan<<<NCHUNKS, SCAN_CHUNK>>>();
    k_bucket<<<(N_EDGES + 255) / 256, 256>>>(rows, cols, vals);

    // Atomic-free aggregation (also covers output zeroing).
    k_agg<<<(N_NODES * 32 + 255) / 256, 256>>>(out);
}

// round 9
// speedup vs baseline: 5.0279x; 1.1460x over previous
#include <cuda_runtime.h>
#include <cuda_fp16.h>

#define N_NODES 100000
#define N_EDGES 1600000
#define DIM 128
#define SCAN_CHUNK 1024
#define NCHUNKS ((N_NODES + SCAN_CHUNK - 1) / SCAN_CHUNK)  // 98
#define SCAN_FLAG (1 << 30)
#define GEMM_BLOCKS ((N_NODES + 63) / 64)          // 1563
#define HIST_BLOCKS ((N_EDGES + 255) / 256)        // 6250

// Static device scratch (allocation-free per harness rules).
// g_cnt / g_aggf are zero at module load and re-zeroed by k_bucket each launch.
__device__ __half g_h[N_NODES * DIM];    // h = x@W + b, fp16    (25.6 MB)
__device__ int    g_cnt[N_NODES];        // per-row edge counts (zero on entry)
__device__ int    g_aggf[NCHUNKS];       // lookback flags      (zero on entry)
__device__ int    g_off[N_NODES + 1];    // CSR row offsets
__device__ int    g_cur[N_NODES];        // bucket cursors
__device__ int2   g_epack[N_EDGES];      // bucketed (col, val-bits) (12.8 MB)

// ---------------------------------------------------------------------------
// Fused kernel: blocks [0, GEMM_BLOCKS) run the HMMA GEMM (64 rows x 128 cols
// per block); blocks [GEMM_BLOCKS, +HIST_BLOCKS) run the edge histogram.
// The two phases are data-independent, so hist hides behind the GEMM wave.
// ---------------------------------------------------------------------------
__global__ void __launch_bounds__(256)
k_gemm_hist(const float* __restrict__ x, const float* __restrict__ W,
            const float* __restrict__ b, const int* __restrict__ rows) {
    if (blockIdx.x >= GEMM_BLOCKS) {
        const int e = (blockIdx.x - GEMM_BLOCKS) * 256 + threadIdx.x;
        if (e < N_EDGES) atomicAdd(&g_cnt[__ldg(&rows[e])], 1);
        return;
    }

    // ---- GEMM tile: 64 rows x 128 cols, K = 128, 8 warps ----
    __shared__ __align__(16) __half xs[64 * 128];    // 16 KB, swizzled
    __shared__ __align__(16) __half ws[128 * 128];   // 32 KB, swizzled

    const int tid  = threadIdx.x;
    const int lane = tid & 31;
    const int warp = tid >> 5;
    const int row0 = blockIdx.x * 64;

    const unsigned xs_base = (unsigned)__cvta_generic_to_shared(xs);
    const unsigned ws_base = (unsigned)__cvta_generic_to_shared(ws);

    // Stage x tile: 64 rows x 128 cols fp32 -> fp16, swizzle ^((r&7)<<4).
#pragma unroll
    for (int it = 0; it < 8; it++) {
        const int idx = tid + it * 256;
        const int r = idx >> 5;        // 0..63
        const int q = idx & 31;        // float4 quad
        const int grow = row0 + r;
        float4 v = make_float4(0.f, 0.f, 0.f, 0.f);
        if (grow < N_NODES) v = *(const float4*)(x + (size_t)grow * DIM + q * 4);
        const __half2 h01 = __floats2half2_rn(v.x, v.y);
        const __half2 h23 = __floats2half2_rn(v.z, v.w);
        const int byte = (r * 256 + q * 8) ^ ((r & 7) << 4);
        *(uint2*)((char*)xs + byte) =
            make_uint2(*(const unsigned*)&h01, *(const unsigned*)&h23);
    }
    // Stage W: full 128 k x 128 n, swizzle ^((k&7)<<4). (L2-hot across blocks.)
#pragma unroll
    for (int it = 0; it < 16; it++) {
        const int idx = tid + it * 256;
        const int k = idx >> 5;        // 0..127
        const int q = idx & 31;        // float4 quad
        const float4 v = *(const float4*)(W + (size_t)k * DIM + q * 4);
        const __half2 h01 = __floats2half2_rn(v.x, v.y);
        const __half2 h23 = __floats2half2_rn(v.z, v.w);
        const int byte = (k * 256 + q * 8) ^ ((k & 7) << 4);
        *(uint2*)((char*)ws + byte) =
            make_uint2(*(const unsigned*)&h01, *(const unsigned*)&h23);
    }
    __syncthreads();

    // Warp layout: warps 0-3 -> rows slabs 0..3 (16 rows each), cols 0..63;
    //              warps 4-7 -> same slabs, cols 64..127.
    const int wr    = warp & 3;
    const int nbase = (warp >> 2) * 64;

    float acc[8][4];
#pragma unroll
    for (int i = 0; i < 8; i++)
#pragma unroll
        for (int j = 0; j < 4; j++) acc[i][j] = 0.f;

    const int ar    = wr * 16 + (lane & 15);
    const int akoff = (lane >> 4) << 3;
    const int bm    = lane >> 3;
    const int bkrow = ((bm & 1) << 3) + (lane & 7);
    const int bnoff = (bm >> 1) << 3;

#pragma unroll
    for (int ks = 0; ks < 8; ks++) {
        const int k0 = ks * 16;
        unsigned a0, a1, a2, a3;
        {
            const int kk = k0 + akoff;
            const unsigned addr =
                xs_base + ((ar * 256 + kk * 2) ^ ((ar & 7) << 4));
            asm volatile(
                "ldmatrix.sync.aligned.m8n8.x4.shared.b16 {%0,%1,%2,%3}, [%4];"
                : "=r"(a0), "=r"(a1), "=r"(a2), "=r"(a3) : "r"(addr));
        }
#pragma unroll
        for (int p = 0; p < 4; p++) {
            unsigned b0, b1, b2, b3;
            const int kk = k0 + bkrow;
            const int nn = nbase + p * 16 + bnoff;
            const unsigned addr =
                ws_base + ((kk * 256 + nn * 2) ^ ((kk & 7) << 4));
            asm volatile(
                "ldmatrix.sync.aligned.m8n8.x4.trans.shared.b16 {%0,%1,%2,%3}, [%4];"
                : "=r"(b0), "=r"(b1), "=r"(b2), "=r"(b3) : "r"(addr));
            asm volatile(
                "mma.sync.aligned.m16n8k16.row.col.f32.f16.f16.f32 "
                "{%0,%1,%2,%3}, {%4,%5,%6,%7}, {%8,%9}, {%0,%1,%2,%3};"
                : "+f"(acc[2 * p][0]), "+f"(acc[2 * p][1]),
                  "+f"(acc[2 * p][2]), "+f"(acc[2 * p][3])
                : "r"(a0), "r"(a1), "r"(a2), "r"(a3), "r"(b0), "r"(b1));
            asm volatile(
                "mma.sync.aligned.m16n8k16.row.col.f32.f16.f16.f32 "
                "{%0,%1,%2,%3}, {%4,%5,%6,%7}, {%8,%9}, {%0,%1,%2,%3};"
                : "+f"(acc[2 * p + 1][0]), "+f"(acc[2 * p + 1][1]),
                  "+f"(acc[2 * p + 1][2]), "+f"(acc[2 * p + 1][3])
                : "r"(a0), "r"(a1), "r"(a2), "r"(a3), "r"(b2), "r"(b3));
        }
    }

    // Epilogue: +bias, fp16 store.
    const int r0 = row0 + wr * 16 + (lane >> 2);
    const int r1 = r0 + 8;
    const int cbase = nbase + ((lane & 3) << 1);
#pragma unroll
    for (int i = 0; i < 8; i++) {
        const int n = cbase + i * 8;
        const float2 bb = *(const float2*)(b + n);
        const __half2 lo = __floats2half2_rn(acc[i][0] + bb.x, acc[i][1] + bb.y);
        const __half2 hi = __floats2half2_rn(acc[i][2] + bb.x, acc[i][3] + bb.y);
        if (r0 < N_NODES) *(__half2*)(g_h + (size_t)r0 * DIM + n) = lo;
        if (r1 < N_NODES) *(__half2*)(g_h + (size_t)r1 * DIM + n) = hi;
    }
}

// ---------------------------------------------------------------------------
// Decoupled-lookback exclusive scan; 98 blocks < 148 SMs -> all wave-1 resident.
// ---------------------------------------------------------------------------
__global__ void __launch_bounds__(1024) k_scan() {
    __shared__ int s[SCAN_CHUNK];
    __shared__ int base_sh;
    const int blk = blockIdx.x;
    const int i = blk * SCAN_CHUNK + threadIdx.x;
    const int v = (i < N_NODES) ? g_cnt[i] : 0;
    s[threadIdx.x] = v;
    __syncthreads();
#pragma unroll
    for (int st = 1; st < SCAN_CHUNK; st <<= 1) {
        const int t = (threadIdx.x >= st) ? s[threadIdx.x - st] : 0;
        __syncthreads();
        s[threadIdx.x] += t;
        __syncthreads();
    }
    if (threadIdx.x == SCAN_CHUNK - 1) {
        __threadfence();
        atomicExch(&g_aggf[blk], s[SCAN_CHUNK - 1] | SCAN_FLAG);
    }
    if (threadIdx.x < 32) {
        int sum = 0;
        for (int p = (int)threadIdx.x; p < blk; p += 32) {
            int a;
            do { a = atomicAdd(&g_aggf[p], 0); } while (!(a & SCAN_FLAG));
            sum += a & ~SCAN_FLAG;
        }
#pragma unroll
        for (int o = 16; o > 0; o >>= 1) sum += __shfl_xor_sync(~0u, sum, o);
        if (threadIdx.x == 0) base_sh = sum;
    }
    __syncthreads();
    if (i < N_NODES) {
        const int excl = base_sh + s[threadIdx.x] - v;
        g_off[i] = excl;
        g_cur[i] = excl;
    }
    if (i == 0) g_off[N_NODES] = N_EDGES;
}

// ---------------------------------------------------------------------------
// Bucket edges into CSR order; also restore the g_cnt/g_aggf zero-invariant
// for the next launch (they are dead after k_scan).
// ---------------------------------------------------------------------------
__global__ void __launch_bounds__(256)
k_bucket(const int* __restrict__ rows, const int* __restrict__ cols,
         const float* __restrict__ vals) {
    const int e = blockIdx.x * 256 + threadIdx.x;
    if (e < N_NODES) g_cnt[e] = 0;
    if (e < NCHUNKS) g_aggf[e] = 0;
    if (e >= N_EDGES) return;
    const int p = atomicAdd(&g_cur[rows[e]], 1);
    g_epack[p] = make_int2(cols[e], __float_as_int(vals[e]));
}

// ---------------------------------------------------------------------------
// Aggregate: one warp per node, fp32 accumulation over fp16 h rows.
// Edge packs batched ahead of gathers for explicit MLP.
// ---------------------------------------------------------------------------
__global__ void __launch_bounds__(256)
k_agg(float* __restrict__ out) {
    const int node = (blockIdx.x * 256 + threadIdx.x) >> 5;
    if (node >= N_NODES) return;
    const int lane = threadIdx.x & 31;
    const int c4 = lane * 4;

    const int start = g_off[node];
    const int end   = g_off[node + 1];

    float4 acc = make_float4(0.f, 0.f, 0.f, 0.f);

    int e = start;
    for (; e + 4 <= end; e += 4) {
        const int2 p0 = g_epack[e + 0];
        const int2 p1 = g_epack[e + 1];
        const int2 p2 = g_epack[e + 2];
        const int2 p3 = g_epack[e + 3];
        const uint2 u0 = *(const uint2*)(g_h + (size_t)p0.x * DIM + c4);
        const uint2 u1 = *(const uint2*)(g_h + (size_t)p1.x * DIM + c4);
        const uint2 u2 = *(const uint2*)(g_h + (size_t)p2.x * DIM + c4);
        const uint2 u3 = *(const uint2*)(g_h + (size_t)p3.x * DIM + c4);
        const float v0 = __int_as_float(p0.y);
        const float v1 = __int_as_float(p1.y);
        const float v2 = __int_as_float(p2.y);
        const float v3 = __int_as_float(p3.y);
        float2 f;
        f = __half22float2(*(const __half2*)&u0.x); acc.x += v0 * f.x; acc.y += v0 * f.y;
        f = __half22float2(*(const __half2*)&u0.y); acc.z += v0 * f.x; acc.w += v0 * f.y;
        f = __half22float2(*(const __half2*)&u1.x); acc.x += v1 * f.x; acc.y += v1 * f.y;
        f = __half22float2(*(const __half2*)&u1.y); acc.z += v1 * f.x; acc.w += v1 * f.y;
        f = __half22float2(*(const __half2*)&u2.x); acc.x += v2 * f.x; acc.y += v2 * f.y;
        f = __half22float2(*(const __half2*)&u2.y); acc.z += v2 * f.x; acc.w += v2 * f.y;
        f = __half22float2(*(const __half2*)&u3.x); acc.x += v3 * f.x; acc.y += v3 * f.y;
        f = __half22float2(*(const __half2*)&u3.y); acc.z += v3 * f.x; acc.w += v3 * f.y;
    }
    for (; e < end; e++) {
        const int2 p = g_epack[e];
        const float v = __int_as_float(p.y);
        const uint2 u = *(const uint2*)(g_h + (size_t)p.x * DIM + c4);
        const float2 f01 = __half22float2(*(const __half2*)&u.x);
        const float2 f23 = __half22float2(*(const __half2*)&u.y);
        acc.x += v * f01.x;
        acc.y += v * f01.y;
        acc.z += v * f23.x;
        acc.w += v * f23.y;
    }

    *(float4*)(out + (size_t)node * DIM + c4) = acc;
}

// ---------------------------------------------------------------------------
// Launcher: 4 plain kernel launches (graph-capture safe).
// ---------------------------------------------------------------------------
extern "C" void kernel_launch(void* const* d_in, const int* in_sizes, int n_in,
                              void* d_out, int out_size) {
    const float* x    = (const float*)d_in[0];
    const float* W    = (const float*)d_in[1];
    const float* b    = (const float*)d_in[2];
    const float* vals = (const float*)d_in[3];
    const int*   rows = (const int*)d_in[4];
    const int*   cols = (const int*)d_in[5];
    float* out = (float*)d_out;

    (void)in_sizes; (void)n_in; (void)out_size;

    k_gemm_hist<<<GEMM_BLOCKS + HIST_BLOCKS, 256>>>(x, W, b, rows);
    k_scan<<<NCHUNKS, SCAN_CHUNK>>>();
    k_bucket<<<(N_EDGES + 255) / 256, 256>>>(rows, cols, vals);
    k_agg<<<(N_NODES * 32 + 255) / 256, 256>>>(out);
}